// round 14
// baseline (speedup 1.0000x reference)
#include <cuda_runtime.h>
#include <math.h>

// Problem constants (fixed shapes from setup_inputs)
#define LL 4
#define BB 8
#define NS 1200
#define NL 128
#define CC 768
#define HH 448
#define WW 448
#define GS 56            // H/8   (grid cols, small)
#define GL 16            // H/28  (grid cols, large)
#define LB (LL*BB)       // 32
#define ROWS_PER_BLK 16          // 8 warps x 2 rows (best k_dist config)
#define NBS (NS/ROWS_PER_BLK)    // 75  (exact)
#define NBL (NL/ROWS_PER_BLK)    // 8   (exact)
#define GDX (NBS+NBL)            // 83

// Scratch (no allocations -> __device__ globals). Device-code refs only.
// Zero-initialized at load; accumulators reset by k_fin each invocation.
// distm: distance with member flag in the sign bit (dist >= 0 always).
__device__ unsigned g_distm_s[LB*NS];
__device__ unsigned g_distm_l[LB*NL];
__device__ unsigned char g_nz_s[LL*NS*8];   // [l][n][b] nonzero flags
__device__ unsigned char g_nz_l[LL*NL*8];
__device__ float g_sp[2*LB];
__device__ float g_sn[2*LB];
__device__ int   g_cp[2*LB];
__device__ int   g_cn[2*LB];

// ---------------------------------------------------------------------------
// 1) Main HBM-bound pass (both scales, one launch).
//    2 rows per warp, streaming float4 loads, anchor in registers, membership
//    prefetched via idx->fk gather (hidden). NEW: each block accumulates its
//    rows' stats contribution directly (inclusion iff own-nz, which implies
//    col_valid); 4 atomic adds per block, hidden under the DRAM loop.
// ---------------------------------------------------------------------------
__global__ void k_dist(const float* __restrict__ sel_s,
                       const float* __restrict__ ker_s,
                       const float* __restrict__ sel_l,
                       const float* __restrict__ ker_l,
                       const float* __restrict__ fk,
                       const int* __restrict__ idx_s,
                       const int* __restrict__ idx_l) {
    __shared__ float sa[CC];
    __shared__ float bsp[8], bsn[8];
    __shared__ int   bcp[8], bcn[8];
    int lb = blockIdx.y;   // l*B + b
    int l  = lb / BB;
    int b  = lb % BB;
    int scale = (blockIdx.x >= NBS) ? 1 : 0;
    int bx = scale ? (blockIdx.x - NBS) : blockIdx.x;
    int N = scale ? NL : NS;
    const float* sel = scale ? sel_l : sel_s;
    const float* ker = scale ? ker_l : ker_s;
    const int*   idx = scale ? idx_l : idx_s;

    int warp = threadIdx.x >> 5;
    int lane = threadIdx.x & 31;
    int n0 = bx * ROWS_PER_BLK + warp;   // rows n0 and n0+8 (no tail: exact)
    int n1 = n0 + 8;

    // --- membership prefetch (lane 0): idx -> fk gather, latency hidden ---
    bool m0 = false, m1 = false;
    if (lane == 0) {
        int G = scale ? GL : GS;
        int S = scale ? 28 : 8;
        int id0 = idx[(size_t)lb * N + n0];
        int id1 = idx[(size_t)lb * N + n1];
        int gi0 = id0 / G, gj0 = id0 % G;
        int gi1 = id1 / G, gj1 = id1 % G;
        m0 = fk[(size_t)b*HH*WW + (size_t)gi0*S*WW + gj0*S] > 0.f;
        m1 = fk[(size_t)b*HH*WW + (size_t)gi1*S*WW + gj1*S] > 0.f;
    }

    // anchor -> smem -> registers
    const float* a = ker + (size_t)lb * CC;   // kernel (L,B,C,1) -> contiguous C
    for (int i = threadIdx.x; i < CC; i += blockDim.x) sa[i] = a[i];
    __syncthreads();

    const float4* av = (const float4*)sa;
    float4 aa[CC/128];
#pragma unroll
    for (int k = 0; k < CC/128; k++) aa[k] = av[k*32 + lane];

    const float4* row0 = (const float4*)(sel + ((size_t)lb * N + n0) * CC);
    const float4* row1 = (const float4*)(sel + ((size_t)lb * N + n1) * CC);

    float s2a = 0.f, saba = 0.f;
    float s2b = 0.f, sabb = 0.f;
#pragma unroll
    for (int k = 0; k < CC/128; k++) {   // 6 iterations, 2x32 float4 each
        float4 v0 = __ldcs(&row0[k*32 + lane]);   // streaming: no reuse
        float4 v1 = __ldcs(&row1[k*32 + lane]);
        float4 A  = aa[k];
        float d0 = A.x - v0.x, d1 = A.y - v0.y, d2 = A.z - v0.z, d3 = A.w - v0.w;
        s2a = fmaf(d0, d0, s2a); s2a = fmaf(d1, d1, s2a);
        s2a = fmaf(d2, d2, s2a); s2a = fmaf(d3, d3, s2a);
        saba += fabsf(v0.x) + fabsf(v0.y) + fabsf(v0.z) + fabsf(v0.w);
        float e0 = A.x - v1.x, e1 = A.y - v1.y, e2 = A.z - v1.z, e3 = A.w - v1.w;
        s2b = fmaf(e0, e0, s2b); s2b = fmaf(e1, e1, s2b);
        s2b = fmaf(e2, e2, s2b); s2b = fmaf(e3, e3, s2b);
        sabb += fabsf(v1.x) + fabsf(v1.y) + fabsf(v1.z) + fabsf(v1.w);
    }
#pragma unroll
    for (int o = 16; o; o >>= 1) {
        s2a  += __shfl_xor_sync(0xFFFFFFFFu, s2a,  o);
        saba += __shfl_xor_sync(0xFFFFFFFFu, saba, o);
        s2b  += __shfl_xor_sync(0xFFFFFFFFu, s2b,  o);
        sabb += __shfl_xor_sync(0xFFFFFFFFu, sabb, o);
    }
    if (lane == 0) {
        float da = sqrtf(s2a), db = sqrtf(s2b);
        unsigned u0 = __float_as_uint(da) | (m0 ? 0x80000000u : 0u);
        unsigned u1 = __float_as_uint(db) | (m1 ? 0x80000000u : 0u);
        // per-warp stats partial: include iff own-nz (implies col_valid)
        float sp = 0.f, sn = 0.f; int cp = 0, cn = 0;
        if (saba != 0.f) { if (m0) { sp += da; cp++; } else { sn += da; cn++; } }
        if (sabb != 0.f) { if (m1) { sp += db; cp++; } else { sn += db; cn++; } }
        bsp[warp] = sp; bsn[warp] = sn; bcp[warp] = cp; bcn[warp] = cn;
        if (scale == 0) {
            g_distm_s[(size_t)lb * NS + n0] = u0;
            g_distm_s[(size_t)lb * NS + n1] = u1;
            g_nz_s[((size_t)l*NS + n0)*8 + b] = (saba != 0.f) ? 1 : 0;
            g_nz_s[((size_t)l*NS + n1)*8 + b] = (sabb != 0.f) ? 1 : 0;
        } else {
            g_distm_l[(size_t)lb * NL + n0] = u0;
            g_distm_l[(size_t)lb * NL + n1] = u1;
            g_nz_l[((size_t)l*NL + n0)*8 + b] = (saba != 0.f) ? 1 : 0;
            g_nz_l[((size_t)l*NL + n1)*8 + b] = (sabb != 0.f) ? 1 : 0;
        }
    }
    __syncthreads();
    if (threadIdx.x == 0) {
        float sp = 0.f, sn = 0.f; int cp = 0, cn = 0;
#pragma unroll
        for (int w2 = 0; w2 < 8; w2++) {
            sp += bsp[w2]; sn += bsn[w2]; cp += bcp[w2]; cn += bcn[w2];
        }
        int gb = scale * LB + lb;
        if (sp != 0.f) atomicAdd(&g_sp[gb], sp);
        if (sn != 0.f) atomicAdd(&g_sn[gb], sn);
        if (cp)        atomicAdd(&g_cp[gb], cp);
        if (cn)        atomicAdd(&g_cn[gb], cn);
    }
}

// ---------------------------------------------------------------------------
// 2) Finalize: ONE block. (a) correction scan: elements with own-nz==0 but
//    col_valid (some other b nonzero) must still be included — found via a
//    zero-byte test on nz words (empty set for typical data, exact always);
//    (b) softplus/act/combine in warp 0; (c) reset accumulators for replay.
// ---------------------------------------------------------------------------
__device__ __forceinline__ bool has_zero_byte(unsigned long long w) {
    return ((w - 0x0101010101010101ULL) & ~w & 0x8080808080808080ULL) != 0ULL;
}

__global__ void k_fin(float* __restrict__ out) {
    int t = threadIdx.x;   // 512 threads

    // --- (a) correction scan: small then large ---
    const unsigned long long* nzs = (const unsigned long long*)g_nz_s;
    for (int i = t; i < LL*NS; i += 512) {
        unsigned long long w = nzs[i];
        if (w != 0ULL && has_zero_byte(w)) {
            int l = i / NS, n = i % NS;
#pragma unroll
            for (int b = 0; b < BB; b++) {
                if (((w >> (8*b)) & 0xFFULL) == 0ULL) {
                    unsigned dm = g_distm_s[(size_t)(l*BB + b)*NS + n];
                    float d = __uint_as_float(dm & 0x7FFFFFFFu);
                    int gb = l*BB + b;   // scale 0
                    if (dm & 0x80000000u) { atomicAdd(&g_sp[gb], d); atomicAdd(&g_cp[gb], 1); }
                    else                  { atomicAdd(&g_sn[gb], d); atomicAdd(&g_cn[gb], 1); }
                }
            }
        }
    }
    const unsigned long long* nzl = (const unsigned long long*)g_nz_l;
    for (int i = t; i < LL*NL; i += 512) {
        unsigned long long w = nzl[i];
        if (w != 0ULL && has_zero_byte(w)) {
            int l = i / NL, n = i % NL;
#pragma unroll
            for (int b = 0; b < BB; b++) {
                if (((w >> (8*b)) & 0xFFULL) == 0ULL) {
                    unsigned dm = g_distm_l[(size_t)(l*BB + b)*NL + n];
                    float d = __uint_as_float(dm & 0x7FFFFFFFu);
                    int gb = LB + l*BB + b;   // scale 1
                    if (dm & 0x80000000u) { atomicAdd(&g_sp[gb], d); atomicAdd(&g_cp[gb], 1); }
                    else                  { atomicAdd(&g_sn[gb], d); atomicAdd(&g_cn[gb], 1); }
                }
            }
        }
    }
    __syncthreads();

    // --- (b) finalize in warp 0: one lane per lb ---
    if (t < 32) {
        int lb = t;
        float sps = g_sp[lb],      sns = g_sn[lb];
        int   cps = g_cp[lb],      cns = g_cn[lb];
        float spl = g_sp[LB + lb], snl = g_sn[LB + lb];
        int   cpl = g_cp[LB + lb], cnl = g_cn[LB + lb];

        float aps = sps / (float)(cps > 1 ? cps : 1);
        float ans = sns / (float)(cns > 1 ? cns : 1);
        float xs = aps - ans;
        float loss_s = (xs > 0.f) ? (xs + log1pf(expf(-xs))) : log1pf(expf(xs));
        int act_s = (cps > 0 && cns > 0);

        float apl = spl / (float)(cpl > 1 ? cpl : 1);
        float anl = snl / (float)(cnl > 1 ? cnl : 1);
        float xl = apl - anl;
        float loss_l = (xl > 0.f) ? (xl + log1pf(expf(-xl))) : log1pf(expf(xl));
        int act_l = (cpl > 0 && cnl > 0) && act_s;

        float v = (act_s ? loss_s : 0.f) + (act_l ? loss_l : 0.f);
        int   c = act_s + act_l;
#pragma unroll
        for (int o = 16; o; o >>= 1) {
            v += __shfl_xor_sync(0xFFFFFFFFu, v, o);
            c += __shfl_xor_sync(0xFFFFFFFFu, c, o);
        }
        if (t == 0)
            out[0] = (c > 0) ? v / (float)c : 0.f;
    }
    __syncthreads();

    // --- (c) reset accumulators for the next (graph-replayed) invocation ---
    if (t < 2*LB) { g_sp[t] = 0.f; g_sn[t] = 0.f; g_cp[t] = 0; g_cn[t] = 0; }
}

// ---------------------------------------------------------------------------
extern "C" void kernel_launch(void* const* d_in, const int* in_sizes, int n_in,
                              void* d_out, int out_size) {
    const float* sel_s = (const float*)d_in[0];
    const int*   idx_s = (const int*)  d_in[1];
    const float* sel_l = (const float*)d_in[2];
    const int*   idx_l = (const int*)  d_in[3];
    const float* ker_s = (const float*)d_in[4];
    const float* ker_l = (const float*)d_in[5];
    const float* fk    = (const float*)d_in[6];

    dim3 gd(GDX, LB);   // (83, 32) = 2656 blocks
    k_dist<<<gd, 256>>>(sel_s, ker_s, sel_l, ker_l, fk, idx_s, idx_l);

    k_fin<<<1, 512>>>((float*)d_out);
}

// round 15
// speedup vs baseline: 1.2977x; 1.2977x over previous
#include <cuda_runtime.h>
#include <math.h>

// Problem constants (fixed shapes from setup_inputs)
#define LL 4
#define BB 8
#define NS 1200
#define NL 128
#define CC 768
#define HH 448
#define WW 448
#define GS 56            // H/8   (grid cols, small)
#define GL 16            // H/28  (grid cols, large)
#define LB (LL*BB)       // 32
#define ROWS_PER_BLK 16          // 8 warps x 2 rows (best k_dist config)
#define NBS (NS/ROWS_PER_BLK)    // 75  (exact)
#define NBL (NL/ROWS_PER_BLK)    // 8   (exact)
#define GDX (NBS+NBL)            // 83
#define STATS_BLOCKS LB          // 32 (one per lb, both scales)

// Scratch (no allocations -> __device__ globals). Device-code refs only.
// distm: distance with member flag in the sign bit (dist >= 0 always).
__device__ unsigned g_distm_s[LB*NS];
__device__ unsigned g_distm_l[LB*NL];
__device__ unsigned char g_nz_s[LL*NS*8];   // [l][n][b] nonzero flags
__device__ unsigned char g_nz_l[LL*NL*8];
__device__ float g_contrib[LB];
__device__ int   g_times  [LB];
__device__ unsigned g_done;

// ---------------------------------------------------------------------------
// 1) Main HBM-bound pass (both scales, one launch).  (R12 config — best.)
//    2 rows per warp, streaming float4 loads (__ldcs), anchor in registers,
//    membership via hidden idx->fk gather, member flag in dist sign bit.
//    PDL: trigger dependent launch early so k_stats' launch latency overlaps.
// ---------------------------------------------------------------------------
__global__ void k_dist(const float* __restrict__ sel_s,
                       const float* __restrict__ ker_s,
                       const float* __restrict__ sel_l,
                       const float* __restrict__ ker_l,
                       const float* __restrict__ fk,
                       const int* __restrict__ idx_s,
                       const int* __restrict__ idx_l) {
    __shared__ float sa[CC];
    int lb = blockIdx.y;   // l*B + b
    int l  = lb / BB;
    int b  = lb % BB;
    int scale = (blockIdx.x >= NBS) ? 1 : 0;
    int bx = scale ? (blockIdx.x - NBS) : blockIdx.x;
    int N = scale ? NL : NS;
    const float* sel = scale ? sel_l : sel_s;
    const float* ker = scale ? ker_l : ker_s;
    const int*   idx = scale ? idx_l : idx_s;

    // PDL: allow the dependent grid (k_stats) to begin launching now; its
    // blocks will block in cudaGridDependencySynchronize() until this grid
    // fully completes (memory-visible). Launch latency overlaps with our work.
#if __CUDA_ARCH__ >= 900
    cudaTriggerProgrammaticLaunchCompletion();
#endif

    int warp = threadIdx.x >> 5;
    int lane = threadIdx.x & 31;
    int n0 = bx * ROWS_PER_BLK + warp;   // rows n0 and n0+8 (no tail: exact)
    int n1 = n0 + 8;

    // --- membership prefetch (lane 0): idx -> fk gather, latency hidden ---
    bool m0 = false, m1 = false;
    if (lane == 0) {
        int G = scale ? GL : GS;
        int S = scale ? 28 : 8;
        int id0 = idx[(size_t)lb * N + n0];
        int id1 = idx[(size_t)lb * N + n1];
        int gi0 = id0 / G, gj0 = id0 % G;
        int gi1 = id1 / G, gj1 = id1 % G;
        m0 = fk[(size_t)b*HH*WW + (size_t)gi0*S*WW + gj0*S] > 0.f;
        m1 = fk[(size_t)b*HH*WW + (size_t)gi1*S*WW + gj1*S] > 0.f;
    }

    // done-counter reset for k_stats (consumed after grid dependency)
    if (blockIdx.x == 0 && blockIdx.y == 0 && threadIdx.x == 32) g_done = 0u;

    // anchor -> smem -> registers
    const float* a = ker + (size_t)lb * CC;   // kernel (L,B,C,1) -> contiguous C
    for (int i = threadIdx.x; i < CC; i += blockDim.x) sa[i] = a[i];
    __syncthreads();

    const float4* av = (const float4*)sa;
    float4 aa[CC/128];
#pragma unroll
    for (int k = 0; k < CC/128; k++) aa[k] = av[k*32 + lane];

    const float4* row0 = (const float4*)(sel + ((size_t)lb * N + n0) * CC);
    const float4* row1 = (const float4*)(sel + ((size_t)lb * N + n1) * CC);

    float s2a = 0.f, saba = 0.f;
    float s2b = 0.f, sabb = 0.f;
#pragma unroll
    for (int k = 0; k < CC/128; k++) {   // 6 iterations, 2x32 float4 each
        float4 v0 = __ldcs(&row0[k*32 + lane]);   // streaming: no reuse
        float4 v1 = __ldcs(&row1[k*32 + lane]);
        float4 A  = aa[k];
        float d0 = A.x - v0.x, d1 = A.y - v0.y, d2 = A.z - v0.z, d3 = A.w - v0.w;
        s2a = fmaf(d0, d0, s2a); s2a = fmaf(d1, d1, s2a);
        s2a = fmaf(d2, d2, s2a); s2a = fmaf(d3, d3, s2a);
        saba += fabsf(v0.x) + fabsf(v0.y) + fabsf(v0.z) + fabsf(v0.w);
        float e0 = A.x - v1.x, e1 = A.y - v1.y, e2 = A.z - v1.z, e3 = A.w - v1.w;
        s2b = fmaf(e0, e0, s2b); s2b = fmaf(e1, e1, s2b);
        s2b = fmaf(e2, e2, s2b); s2b = fmaf(e3, e3, s2b);
        sabb += fabsf(v1.x) + fabsf(v1.y) + fabsf(v1.z) + fabsf(v1.w);
    }
#pragma unroll
    for (int o = 16; o; o >>= 1) {
        s2a  += __shfl_xor_sync(0xFFFFFFFFu, s2a,  o);
        saba += __shfl_xor_sync(0xFFFFFFFFu, saba, o);
        s2b  += __shfl_xor_sync(0xFFFFFFFFu, s2b,  o);
        sabb += __shfl_xor_sync(0xFFFFFFFFu, sabb, o);
    }
    if (lane == 0) {
        unsigned u0 = __float_as_uint(sqrtf(s2a)) | (m0 ? 0x80000000u : 0u);
        unsigned u1 = __float_as_uint(sqrtf(s2b)) | (m1 ? 0x80000000u : 0u);
        if (scale == 0) {
            g_distm_s[(size_t)lb * NS + n0] = u0;
            g_distm_s[(size_t)lb * NS + n1] = u1;
            g_nz_s[((size_t)l*NS + n0)*8 + b] = (saba != 0.f) ? 1 : 0;
            g_nz_s[((size_t)l*NS + n1)*8 + b] = (sabb != 0.f) ? 1 : 0;
        } else {
            g_distm_l[(size_t)lb * NL + n0] = u0;
            g_distm_l[(size_t)lb * NL + n1] = u1;
            g_nz_l[((size_t)l*NL + n0)*8 + b] = (saba != 0.f) ? 1 : 0;
            g_nz_l[((size_t)l*NL + n1)*8 + b] = (sabb != 0.f) ? 1 : 0;
        }
    }
}

// ---------------------------------------------------------------------------
// 2) Stats: one block per lb, BOTH scales local; PDL-gated on k_dist.
// ---------------------------------------------------------------------------
__global__ void k_stats(float* __restrict__ out) {
#if __CUDA_ARCH__ >= 900
    cudaGridDependencySynchronize();   // wait for k_dist completion+visibility
#endif
    int lb = blockIdx.x;
    int l = lb / BB;
    int t = threadIdx.x;

    // ---- gather: 5 small chunks + 1 large chunk, all independent (MLP) ----
    unsigned long long w[6];
    unsigned dm[6];
#pragma unroll
    for (int k = 0; k < 5; k++) {      // small scale: n = k*256 + t < 1200
        int n = k * 256 + t;
        bool ok = n < NS;
        w[k]  = ok ? *(const unsigned long long*)(g_nz_s + ((size_t)l*NS + n)*8) : 0ull;
        dm[k] = ok ? g_distm_s[(size_t)lb*NS + n] : 0u;
    }
    {                                   // large scale: n = t < 128
        bool ok = t < NL;
        int n = ok ? t : 0;
        w[5]  = ok ? *(const unsigned long long*)(g_nz_l + ((size_t)l*NL + n)*8) : 0ull;
        dm[5] = ok ? g_distm_l[(size_t)lb*NL + n] : 0u;
    }

    float sps = 0.f, sns = 0.f, spl = 0.f, snl = 0.f;
    int   cps = 0,   cns = 0,   cpl = 0,   cnl = 0;
#pragma unroll
    for (int k = 0; k < 5; k++) {
        if (w[k] != 0ull) {
            float d = __uint_as_float(dm[k] & 0x7FFFFFFFu);
            if (dm[k] & 0x80000000u) { sps += d; cps++; } else { sns += d; cns++; }
        }
    }
    if (w[5] != 0ull) {
        float d = __uint_as_float(dm[5] & 0x7FFFFFFFu);
        if (dm[5] & 0x80000000u) { spl += d; cpl++; } else { snl += d; cnl++; }
    }

    // ---- deterministic block reduce (8 quantities) ----
#pragma unroll
    for (int o = 16; o; o >>= 1) {
        sps += __shfl_xor_sync(0xFFFFFFFFu, sps, o);
        sns += __shfl_xor_sync(0xFFFFFFFFu, sns, o);
        spl += __shfl_xor_sync(0xFFFFFFFFu, spl, o);
        snl += __shfl_xor_sync(0xFFFFFFFFu, snl, o);
        cps += __shfl_xor_sync(0xFFFFFFFFu, cps, o);
        cns += __shfl_xor_sync(0xFFFFFFFFu, cns, o);
        cpl += __shfl_xor_sync(0xFFFFFFFFu, cpl, o);
        cnl += __shfl_xor_sync(0xFFFFFFFFu, cnl, o);
    }
    __shared__ float r0[8], r1[8], r2[8], r3[8];
    __shared__ int   c0[8], c1[8], c2[8], c3[8];
    int warp = t >> 5;
    if ((t & 31) == 0) {
        r0[warp]=sps; r1[warp]=sns; r2[warp]=spl; r3[warp]=snl;
        c0[warp]=cps; c1[warp]=cns; c2[warp]=cpl; c3[warp]=cnl;
    }
    __syncthreads();
    if (t == 0) {
        float tsps=0.f, tsns=0.f, tspl=0.f, tsnl=0.f;
        int   tcps=0,   tcns=0,   tcpl=0,   tcnl=0;
#pragma unroll
        for (int v = 0; v < 8; v++) {
            tsps+=r0[v]; tsns+=r1[v]; tspl+=r2[v]; tsnl+=r3[v];
            tcps+=c0[v]; tcns+=c1[v]; tcpl+=c2[v]; tcnl+=c3[v];
        }
        float aps = tsps / (float)(tcps > 1 ? tcps : 1);
        float ans = tsns / (float)(tcns > 1 ? tcns : 1);
        float xs = aps - ans;
        float loss_s = (xs > 0.f) ? (xs + log1pf(expf(-xs))) : log1pf(expf(xs));
        int act_s = (tcps > 0 && tcns > 0);

        float apl = tspl / (float)(tcpl > 1 ? tcpl : 1);
        float anl = tsnl / (float)(tcnl > 1 ? tcnl : 1);
        float xl = apl - anl;
        float loss_l = (xl > 0.f) ? (xl + log1pf(expf(-xl))) : log1pf(expf(xl));
        int act_l = (tcpl > 0 && tcnl > 0) && act_s;

        g_contrib[lb] = (act_s ? loss_s : 0.f) + (act_l ? loss_l : 0.f);
        g_times  [lb] = act_s + act_l;
    }

    // ---- last-block combine (tiny, deterministic) ----
    __shared__ bool is_last;
    __syncthreads();
    if (t == 0) {
        __threadfence();
        unsigned prev = atomicAdd(&g_done, 1u);
        is_last = (prev == STATS_BLOCKS - 1);
    }
    __syncthreads();
    if (!is_last) return;
    __threadfence();

    if (t < 32) {
        float v = g_contrib[t];
        int   c = g_times[t];
#pragma unroll
        for (int o = 16; o; o >>= 1) {
            v += __shfl_xor_sync(0xFFFFFFFFu, v, o);
            c += __shfl_xor_sync(0xFFFFFFFFu, c, o);
        }
        if (t == 0)
            out[0] = (c > 0) ? v / (float)c : 0.f;
    }
}

// ---------------------------------------------------------------------------
extern "C" void kernel_launch(void* const* d_in, const int* in_sizes, int n_in,
                              void* d_out, int out_size) {
    const float* sel_s = (const float*)d_in[0];
    const int*   idx_s = (const int*)  d_in[1];
    const float* sel_l = (const float*)d_in[2];
    const int*   idx_l = (const int*)  d_in[3];
    const float* ker_s = (const float*)d_in[4];
    const float* ker_l = (const float*)d_in[5];
    const float* fk    = (const float*)d_in[6];

    dim3 gd(GDX, LB);   // (83, 32) = 2656 blocks
    k_dist<<<gd, 256>>>(sel_s, ker_s, sel_l, ker_l, fk, idx_s, idx_l);

    // k_stats via PDL: launch overlaps k_dist's execution; griddepsync gates.
    cudaLaunchConfig_t cfg = {};
    cfg.gridDim  = dim3(STATS_BLOCKS, 1, 1);
    cfg.blockDim = dim3(256, 1, 1);
    cfg.dynamicSmemBytes = 0;
    cfg.stream = 0;   // legacy default stream (same as <<<>>> above)
    cudaLaunchAttribute attrs[1];
    attrs[0].id = cudaLaunchAttributeProgrammaticStreamSerialization;
    attrs[0].val.programmaticStreamSerializationAllowed = 1;
    cfg.attrs = attrs;
    cfg.numAttrs = 1;
    float* outp = (float*)d_out;
    cudaLaunchKernelEx(&cfg, k_stats, outp);
}

// round 16
// speedup vs baseline: 1.2989x; 1.0010x over previous
#include <cuda_runtime.h>
#include <math.h>

// Problem constants (fixed shapes from setup_inputs)
#define LL 4
#define BB 8
#define NS 1200
#define NL 128
#define CC 768
#define HH 448
#define WW 448
#define GS 56            // H/8   (grid cols, small)
#define GL 16            // H/28  (grid cols, large)
#define LB (LL*BB)       // 32
#define ROWS_PER_BLK 32          // 16 warps x 2 rows, 512 threads
#define NBS ((NS + ROWS_PER_BLK - 1) / ROWS_PER_BLK)   // 38 (tail guarded)
#define NBL (NL / ROWS_PER_BLK)                        // 4
#define GDX (NBS + NBL)          // 42
#define STATS_BLOCKS LB          // 32 (one per lb, both scales)

// Scratch (no allocations -> __device__ globals). Device-code refs only.
// distm: distance with member flag in the sign bit (dist >= 0 always).
__device__ unsigned g_distm_s[LB*NS];
__device__ unsigned g_distm_l[LB*NL];
__device__ unsigned char g_nz_s[LL*NS*8];   // [l][n][b] nonzero flags
__device__ unsigned char g_nz_l[LL*NL*8];
__device__ float g_contrib[LB];
__device__ int   g_times  [LB];
__device__ unsigned g_done;

// ---------------------------------------------------------------------------
// 1) Main HBM-bound pass (both scales, one launch).
//    512 threads, 16 warps x 2 rows; NO smem, NO syncthreads — anchor loaded
//    straight to registers from L2-hot kernel tensor. Membership via hidden
//    idx->fk gather; member flag in dist sign bit. PDL trigger for k_stats.
// ---------------------------------------------------------------------------
__global__ void __launch_bounds__(512)
k_dist(const float* __restrict__ sel_s,
       const float* __restrict__ ker_s,
       const float* __restrict__ sel_l,
       const float* __restrict__ ker_l,
       const float* __restrict__ fk,
       const int* __restrict__ idx_s,
       const int* __restrict__ idx_l) {
    int lb = blockIdx.y;   // l*B + b
    int l  = lb / BB;
    int b  = lb % BB;
    int scale = (blockIdx.x >= NBS) ? 1 : 0;
    int bx = scale ? (blockIdx.x - NBS) : blockIdx.x;
    int N = scale ? NL : NS;
    const float* sel = scale ? sel_l : sel_s;
    const float* ker = scale ? ker_l : ker_s;
    const int*   idx = scale ? idx_l : idx_s;

#if __CUDA_ARCH__ >= 900
    cudaTriggerProgrammaticLaunchCompletion();
#endif

    int warp = threadIdx.x >> 5;   // 0..15
    int lane = threadIdx.x & 31;
    int n0 = bx * ROWS_PER_BLK + warp;   // rows n0 and n0+16
    int n1 = n0 + 16;
    bool live0 = (n0 < N);               // tail block: n1 rows may be dead
    bool live1 = (n1 < N);
    int n0c = live0 ? n0 : (N - 1);
    int n1c = live1 ? n1 : (N - 1);

    // --- membership prefetch (lane 0): idx -> fk gather, latency hidden ---
    bool m0 = false, m1 = false;
    if (lane == 0) {
        int G = scale ? GL : GS;
        int S = scale ? 28 : 8;
        int id0 = idx[(size_t)lb * N + n0c];
        int id1 = idx[(size_t)lb * N + n1c];
        int gi0 = id0 / G, gj0 = id0 % G;
        int gi1 = id1 / G, gj1 = id1 % G;
        m0 = fk[(size_t)b*HH*WW + (size_t)gi0*S*WW + gj0*S] > 0.f;
        m1 = fk[(size_t)b*HH*WW + (size_t)gi1*S*WW + gj1*S] > 0.f;
    }

    // done-counter reset for k_stats (consumed after grid dependency)
    if (blockIdx.x == 0 && blockIdx.y == 0 && threadIdx.x == 32) g_done = 0u;

    // anchor -> registers directly (kernel tensor is tiny and L2-hot)
    const float4* kerv = (const float4*)(ker + (size_t)lb * CC);
    float4 aa[CC/128];
#pragma unroll
    for (int k = 0; k < CC/128; k++) aa[k] = __ldg(&kerv[k*32 + lane]);

    const float4* row0 = (const float4*)(sel + ((size_t)lb * N + n0c) * CC);
    const float4* row1 = (const float4*)(sel + ((size_t)lb * N + n1c) * CC);

    float s2a = 0.f, saba = 0.f;
    float s2b = 0.f, sabb = 0.f;
#pragma unroll
    for (int k = 0; k < CC/128; k++) {   // 6 iterations, 2x32 float4 each
        float4 v0 = __ldcs(&row0[k*32 + lane]);   // streaming: no reuse
        float4 v1 = __ldcs(&row1[k*32 + lane]);
        float4 A  = aa[k];
        float d0 = A.x - v0.x, d1 = A.y - v0.y, d2 = A.z - v0.z, d3 = A.w - v0.w;
        s2a = fmaf(d0, d0, s2a); s2a = fmaf(d1, d1, s2a);
        s2a = fmaf(d2, d2, s2a); s2a = fmaf(d3, d3, s2a);
        saba += fabsf(v0.x) + fabsf(v0.y) + fabsf(v0.z) + fabsf(v0.w);
        float e0 = A.x - v1.x, e1 = A.y - v1.y, e2 = A.z - v1.z, e3 = A.w - v1.w;
        s2b = fmaf(e0, e0, s2b); s2b = fmaf(e1, e1, s2b);
        s2b = fmaf(e2, e2, s2b); s2b = fmaf(e3, e3, s2b);
        sabb += fabsf(v1.x) + fabsf(v1.y) + fabsf(v1.z) + fabsf(v1.w);
    }
#pragma unroll
    for (int o = 16; o; o >>= 1) {
        s2a  += __shfl_xor_sync(0xFFFFFFFFu, s2a,  o);
        saba += __shfl_xor_sync(0xFFFFFFFFu, saba, o);
        s2b  += __shfl_xor_sync(0xFFFFFFFFu, s2b,  o);
        sabb += __shfl_xor_sync(0xFFFFFFFFu, sabb, o);
    }
    if (lane == 0) {
        unsigned u0 = __float_as_uint(sqrtf(s2a)) | (m0 ? 0x80000000u : 0u);
        unsigned u1 = __float_as_uint(sqrtf(s2b)) | (m1 ? 0x80000000u : 0u);
        if (scale == 0) {
            if (live0) {
                g_distm_s[(size_t)lb * NS + n0] = u0;
                g_nz_s[((size_t)l*NS + n0)*8 + b] = (saba != 0.f) ? 1 : 0;
            }
            if (live1) {
                g_distm_s[(size_t)lb * NS + n1] = u1;
                g_nz_s[((size_t)l*NS + n1)*8 + b] = (sabb != 0.f) ? 1 : 0;
            }
        } else {
            g_distm_l[(size_t)lb * NL + n0] = u0;
            g_distm_l[(size_t)lb * NL + n1] = u1;
            g_nz_l[((size_t)l*NL + n0)*8 + b] = (saba != 0.f) ? 1 : 0;
            g_nz_l[((size_t)l*NL + n1)*8 + b] = (sabb != 0.f) ? 1 : 0;
        }
    }
}

// ---------------------------------------------------------------------------
// 2) Stats: one block per lb, BOTH scales local; PDL-gated on k_dist.
// ---------------------------------------------------------------------------
__global__ void k_stats(float* __restrict__ out) {
#if __CUDA_ARCH__ >= 900
    cudaGridDependencySynchronize();   // wait for k_dist completion+visibility
#endif
    int lb = blockIdx.x;
    int l = lb / BB;
    int t = threadIdx.x;

    // ---- gather: 5 small chunks + 1 large chunk, all independent (MLP) ----
    unsigned long long w[6];
    unsigned dm[6];
#pragma unroll
    for (int k = 0; k < 5; k++) {      // small scale: n = k*256 + t < 1200
        int n = k * 256 + t;
        bool ok = n < NS;
        w[k]  = ok ? *(const unsigned long long*)(g_nz_s + ((size_t)l*NS + n)*8) : 0ull;
        dm[k] = ok ? g_distm_s[(size_t)lb*NS + n] : 0u;
    }
    {                                   // large scale: n = t < 128
        bool ok = t < NL;
        int n = ok ? t : 0;
        w[5]  = ok ? *(const unsigned long long*)(g_nz_l + ((size_t)l*NL + n)*8) : 0ull;
        dm[5] = ok ? g_distm_l[(size_t)lb*NL + n] : 0u;
    }

    float sps = 0.f, sns = 0.f, spl = 0.f, snl = 0.f;
    int   cps = 0,   cns = 0,   cpl = 0,   cnl = 0;
#pragma unroll
    for (int k = 0; k < 5; k++) {
        if (w[k] != 0ull) {
            float d = __uint_as_float(dm[k] & 0x7FFFFFFFu);
            if (dm[k] & 0x80000000u) { sps += d; cps++; } else { sns += d; cns++; }
        }
    }
    if (w[5] != 0ull) {
        float d = __uint_as_float(dm[5] & 0x7FFFFFFFu);
        if (dm[5] & 0x80000000u) { spl += d; cpl++; } else { snl += d; cnl++; }
    }

    // ---- deterministic block reduce (8 quantities) ----
#pragma unroll
    for (int o = 16; o; o >>= 1) {
        sps += __shfl_xor_sync(0xFFFFFFFFu, sps, o);
        sns += __shfl_xor_sync(0xFFFFFFFFu, sns, o);
        spl += __shfl_xor_sync(0xFFFFFFFFu, spl, o);
        snl += __shfl_xor_sync(0xFFFFFFFFu, snl, o);
        cps += __shfl_xor_sync(0xFFFFFFFFu, cps, o);
        cns += __shfl_xor_sync(0xFFFFFFFFu, cns, o);
        cpl += __shfl_xor_sync(0xFFFFFFFFu, cpl, o);
        cnl += __shfl_xor_sync(0xFFFFFFFFu, cnl, o);
    }
    __shared__ float r0[8], r1[8], r2[8], r3[8];
    __shared__ int   c0[8], c1[8], c2[8], c3[8];
    int warp = t >> 5;
    if ((t & 31) == 0) {
        r0[warp]=sps; r1[warp]=sns; r2[warp]=spl; r3[warp]=snl;
        c0[warp]=cps; c1[warp]=cns; c2[warp]=cpl; c3[warp]=cnl;
    }
    __syncthreads();
    if (t == 0) {
        float tsps=0.f, tsns=0.f, tspl=0.f, tsnl=0.f;
        int   tcps=0,   tcns=0,   tcpl=0,   tcnl=0;
#pragma unroll
        for (int v = 0; v < 8; v++) {
            tsps+=r0[v]; tsns+=r1[v]; tspl+=r2[v]; tsnl+=r3[v];
            tcps+=c0[v]; tcns+=c1[v]; tcpl+=c2[v]; tcnl+=c3[v];
        }
        float aps = tsps / (float)(tcps > 1 ? tcps : 1);
        float ans = tsns / (float)(tcns > 1 ? tcns : 1);
        float xs = aps - ans;
        float loss_s = (xs > 0.f) ? (xs + log1pf(expf(-xs))) : log1pf(expf(xs));
        int act_s = (tcps > 0 && tcns > 0);

        float apl = tspl / (float)(tcpl > 1 ? tcpl : 1);
        float anl = tsnl / (float)(tcnl > 1 ? tcnl : 1);
        float xl = apl - anl;
        float loss_l = (xl > 0.f) ? (xl + log1pf(expf(-xl))) : log1pf(expf(xl));
        int act_l = (tcpl > 0 && tcnl > 0) && act_s;

        g_contrib[lb] = (act_s ? loss_s : 0.f) + (act_l ? loss_l : 0.f);
        g_times  [lb] = act_s + act_l;
    }

    // ---- last-block combine (tiny, deterministic) ----
    __shared__ bool is_last;
    __syncthreads();
    if (t == 0) {
        __threadfence();
        unsigned prev = atomicAdd(&g_done, 1u);
        is_last = (prev == STATS_BLOCKS - 1);
    }
    __syncthreads();
    if (!is_last) return;
    __threadfence();

    if (t < 32) {
        float v = g_contrib[t];
        int   c = g_times[t];
#pragma unroll
        for (int o = 16; o; o >>= 1) {
            v += __shfl_xor_sync(0xFFFFFFFFu, v, o);
            c += __shfl_xor_sync(0xFFFFFFFFu, c, o);
        }
        if (t == 0)
            out[0] = (c > 0) ? v / (float)c : 0.f;
    }
}

// ---------------------------------------------------------------------------
extern "C" void kernel_launch(void* const* d_in, const int* in_sizes, int n_in,
                              void* d_out, int out_size) {
    const float* sel_s = (const float*)d_in[0];
    const int*   idx_s = (const int*)  d_in[1];
    const float* sel_l = (const float*)d_in[2];
    const int*   idx_l = (const int*)  d_in[3];
    const float* ker_s = (const float*)d_in[4];
    const float* ker_l = (const float*)d_in[5];
    const float* fk    = (const float*)d_in[6];

    dim3 gd(GDX, LB);   // (42, 32) = 1344 blocks, 512 threads each
    k_dist<<<gd, 512>>>(sel_s, ker_s, sel_l, ker_l, fk, idx_s, idx_l);

    // k_stats via PDL (neutral but harmless; keeps launch overlapped).
    cudaLaunchConfig_t cfg = {};
    cfg.gridDim  = dim3(STATS_BLOCKS, 1, 1);
    cfg.blockDim = dim3(256, 1, 1);
    cfg.dynamicSmemBytes = 0;
    cfg.stream = 0;
    cudaLaunchAttribute attrs[1];
    attrs[0].id = cudaLaunchAttributeProgrammaticStreamSerialization;
    attrs[0].val.programmaticStreamSerializationAllowed = 1;
    cfg.attrs = attrs;
    cfg.numAttrs = 1;
    float* outp = (float*)d_out;
    cudaLaunchKernelEx(&cfg, k_stats, outp);
}